// round 9
// baseline (speedup 1.0000x reference)
#include <cuda_runtime.h>
#include <cstdint>

#define DEV __device__ __forceinline__

// ---------------- problem constants ----------------
static constexpr int T_TOK = 8192;          // B*S = 4*2048
static constexpr int HID   = 1024;
static constexpr int FFND  = 4096;
static constexpr int NE    = 8;
static constexpr int ROWS_PAD = 17408;      // 16384 + 8*128 pad, = 136*128

// ---------------- device scratch (bss, no allocations) ----------------
__device__ float g_hmid[(size_t)ROWS_PAD * FFND];   // permuted fc1 output
__device__ float g_out2[(size_t)ROWS_PAD * HID];    // per-slot fc2 contribution
__device__ int   g_perm_token[ROWS_PAD];            // padded rows = -1
__device__ int   g_pos[T_TOK * 2];                  // token slot -> permuted row
__device__ int   g_topk_idx[T_TOK * 2];
__device__ float g_topk_w[T_TOK * 2];
__device__ int   g_counts[NE];
__device__ int   g_fill[NE];
__device__ int   g_offp[NE + 1];                    // padded exclusive offsets

// ---------------- PTX helpers ----------------
DEV uint32_t smem_u32(const void* p) {
    uint32_t a;
    asm("{ .reg .u64 t; cvta.to.shared.u64 t, %1; cvt.u32.u64 %0, t; }" : "=r"(a) : "l"(p));
    return a;
}
DEV uint32_t tf32(float f) {
    uint32_t r;
    asm("cvt.rna.tf32.f32 %0, %1;" : "=r"(r) : "f"(f));
    return r;
}
DEV void cpa16(uint32_t dst, const void* src, bool v) {
    int sz = v ? 16 : 0;
    asm volatile("cp.async.cg.shared.global [%0], [%1], 16, %2;"
                 :: "r"(dst), "l"(src), "r"(sz) : "memory");
}
DEV void cp_commit() { asm volatile("cp.async.commit_group;" ::: "memory"); }
DEV void cp_wait1()  { asm volatile("cp.async.wait_group 1;" ::: "memory"); }

DEV void mma8(float* c, const uint32_t* a, const uint32_t* b) {
    asm volatile(
        "mma.sync.aligned.m16n8k8.row.col.f32.tf32.tf32.f32 "
        "{%0,%1,%2,%3}, {%4,%5,%6,%7}, {%8,%9}, {%0,%1,%2,%3};"
        : "+f"(c[0]), "+f"(c[1]), "+f"(c[2]), "+f"(c[3])
        : "r"(a[0]), "r"(a[1]), "r"(a[2]), "r"(a[3]), "r"(b[0]), "r"(b[1]));
}

// swizzled smem float index for a 128x32 tile (row*32 floats, 4-float XOR units)
DEV int sidx(int row, int k) {
    return row * 32 + ((((k >> 2) ^ (row & 7))) << 2) + (k & 3);
}
DEV float silu(float x) { return x / (1.0f + expf(-x)); }

// ---------------- small kernels ----------------
__global__ void k_init() {
    int i = blockIdx.x * 256 + threadIdx.x;
    if (i < ROWS_PAD) g_perm_token[i] = -1;
    if (i < NE) { g_counts[i] = 0; g_fill[i] = 0; }
}

__global__ __launch_bounds__(256) void k_router(const float* __restrict__ x,
                                                const float* __restrict__ Wr) {
    __shared__ float wr[NE * HID];  // 32 KB
    int tid = threadIdx.x;
    for (int i = tid; i < NE * HID; i += 256) wr[i] = Wr[i];
    __syncthreads();
    int warp = tid >> 5, lane = tid & 31;
    int t = blockIdx.x * 8 + warp;
    const float* xr = x + (size_t)t * HID;
    float acc[NE];
#pragma unroll
    for (int e = 0; e < NE; e++) acc[e] = 0.f;
    for (int i = lane; i < HID; i += 32) {
        float xv = xr[i];
#pragma unroll
        for (int e = 0; e < NE; e++) acc[e] = fmaf(xv, wr[e * HID + i], acc[e]);
    }
#pragma unroll
    for (int e = 0; e < NE; e++)
#pragma unroll
        for (int o = 16; o > 0; o >>= 1) acc[e] += __shfl_xor_sync(0xFFFFFFFFu, acc[e], o);
    if (lane == 0) {
        float m = acc[0];
#pragma unroll
        for (int e = 1; e < NE; e++) m = fmaxf(m, acc[e]);
        float p[NE], s = 0.f;
#pragma unroll
        for (int e = 0; e < NE; e++) { p[e] = expf(acc[e] - m); s += p[e]; }
        float inv = 1.f / s;
#pragma unroll
        for (int e = 0; e < NE; e++) p[e] *= inv;
        int e0 = 0;
#pragma unroll
        for (int e = 1; e < NE; e++) if (p[e] > p[e0]) e0 = e;
        int e1 = (e0 == 0) ? 1 : 0;
#pragma unroll
        for (int e = 0; e < NE; e++) if (e != e0 && p[e] > p[e1]) e1 = e;
        g_topk_idx[2 * t] = e0;    g_topk_idx[2 * t + 1] = e1;
        g_topk_w[2 * t]   = p[e0]; g_topk_w[2 * t + 1]   = p[e1];
        atomicAdd(&g_counts[e0], 1);
        atomicAdd(&g_counts[e1], 1);
    }
}

__global__ void k_offsets() {
    if (threadIdx.x == 0 && blockIdx.x == 0) {
        int a = 0;
        for (int e = 0; e < NE; e++) {
            g_offp[e] = a;
            a += ((g_counts[e] + 127) >> 7) << 7;
        }
        g_offp[NE] = a;
    }
}

__global__ void k_scatter() {
    int t = blockIdx.x * 256 + threadIdx.x;
    if (t >= T_TOK) return;
#pragma unroll
    for (int s = 0; s < 2; s++) {
        int e = g_topk_idx[2 * t + s];
        int pos = g_offp[e] + atomicAdd(&g_fill[e], 1);
        g_perm_token[pos] = t;
        g_pos[2 * t + s] = pos;
    }
}

__global__ void k_combine(float* __restrict__ out) {
    int t = blockIdx.x;
    int c = threadIdx.x * 4;
    float w0 = g_topk_w[2 * t], w1 = g_topk_w[2 * t + 1];
    int p0 = g_pos[2 * t], p1 = g_pos[2 * t + 1];
    float4 a = *(const float4*)&g_out2[(size_t)p0 * HID + c];
    float4 b = *(const float4*)&g_out2[(size_t)p1 * HID + c];
    float4 o;
    o.x = w0 * a.x + w1 * b.x;
    o.y = w0 * a.y + w1 * b.y;
    o.z = w0 * a.z + w1 * b.z;
    o.w = w0 * a.w + w1 * b.w;
    *(float4*)&out[(size_t)t * HID + c] = o;
}

// ---------------- grouped GEMM (tf32 mma.sync) ----------------
// FC1:  out = silu(X[perm] @ W1[e]^T + b1[e])  -> g_hmid   (K=1024, N=4096)
// FC2:  out =       g_hmid @ W2[e]^T + b2[e]   -> g_out2   (K=4096, N=1024)
// Tile 128x128, BK=32, 256 threads (8 warps in 2x4, warp tile 64x32),
// double-buffered cp.async, XOR-swizzled smem, per-element cvt.rna.tf32.

template <bool FC1>
__global__ __launch_bounds__(256, 2) void k_gemm(const float* __restrict__ A0,
                                                 const float* __restrict__ W,
                                                 const float* __restrict__ bias) {
    constexpr int K    = FC1 ? HID : FFND;
    constexpr int NTOT = FC1 ? FFND : HID;
    constexpr int KT   = K / 32;

    extern __shared__ float sm[];          // 2 * (128x32 A + 128x32 B) = 64 KB
    __shared__ int s_tok[128];

    const int tid = threadIdx.x;
    const int rbase = blockIdx.y * 128;
    const int nbase = blockIdx.x * 128;

    int e = 0;
    while (e < NE - 1 && rbase >= g_offp[e + 1]) e++;
    const float* Wexp = W + (size_t)e * NTOT * K;
    const float* Bias = bias + (size_t)e * NTOT;

    if (FC1) {
        if (tid < 128) s_tok[tid] = g_perm_token[rbase + tid];
        __syncthreads();
    }

    const uint32_t sbase = smem_u32(sm);
    const float* Ain = FC1 ? A0 : g_hmid;
    float* Out = FC1 ? g_hmid : g_out2;

    // per-thread load descriptors: 4 x 16B for A, 4 x 16B for B per buffer
    const float* srcA[4];
    const float* srcB[4];
    uint32_t dstA[4], dstB[4];
    bool vA[4];
#pragma unroll
    for (int i = 0; i < 4; i++) {
        int lin = tid + i * 256, row = lin >> 3, u = lin & 7;
        dstA[i] = sbase + row * 128 + ((u ^ (row & 7)) << 4);
        dstB[i] = sbase + 16384 + row * 128 + ((u ^ (row & 7)) << 4);
        if (FC1) {
            int tok = s_tok[row];
            vA[i] = (tok >= 0);
            srcA[i] = Ain + (size_t)(tok < 0 ? 0 : tok) * K + u * 4;
        } else {
            vA[i] = true;
            srcA[i] = Ain + (size_t)(rbase + row) * K + u * 4;
        }
        srcB[i] = Wexp + (size_t)(nbase + row) * K + u * 4;
    }

    float acc[4][4][4];
#pragma unroll
    for (int mi = 0; mi < 4; mi++)
#pragma unroll
        for (int ni = 0; ni < 4; ni++)
#pragma unroll
            for (int c = 0; c < 4; c++) acc[mi][ni][c] = 0.f;

    const int warp = tid >> 5, lane = tid & 31;
    const int wm = (warp >> 2) * 64, wn = (warp & 3) * 32;

#define LOAD_TILE(buf)                                                        \
    do {                                                                      \
        uint32_t boff = (uint32_t)(buf) * 32768u;                             \
        _Pragma("unroll") for (int i = 0; i < 4; i++) {                       \
            cpa16(dstA[i] + boff, srcA[i], vA[i]); srcA[i] += 32;             \
        }                                                                     \
        _Pragma("unroll") for (int i = 0; i < 4; i++) {                       \
            cpa16(dstB[i] + boff, srcB[i], true); srcB[i] += 32;              \
        }                                                                     \
    } while (0)

#define COMPUTE(buf)                                                          \
    do {                                                                      \
        const float* sA = sm + (buf) * 8192;                                  \
        const float* sB = sA + 4096;                                          \
        _Pragma("unroll") for (int kk = 0; kk < 4; kk++) {                    \
            int k0 = kk * 8 + (lane & 3);                                     \
            uint32_t af[4][4], bf[4][2];                                      \
            _Pragma("unroll") for (int mi = 0; mi < 4; mi++) {                \
                int r0 = wm + mi * 16 + (lane >> 2);                          \
                af[mi][0] = tf32(sA[sidx(r0,     k0)]);                       \
                af[mi][1] = tf32(sA[sidx(r0 + 8, k0)]);                       \
                af[mi][2] = tf32(sA[sidx(r0,     k0 + 4)]);                   \
                af[mi][3] = tf32(sA[sidx(r0 + 8, k0 + 4)]);                   \
            }                                                                 \
            _Pragma("unroll") for (int ni = 0; ni < 4; ni++) {                \
                int n0 = wn + ni * 8 + (lane >> 2);                           \
                bf[ni][0] = tf32(sB[sidx(n0, k0)]);                           \
                bf[ni][1] = tf32(sB[sidx(n0, k0 + 4)]);                       \
            }                                                                 \
            _Pragma("unroll") for (int mi = 0; mi < 4; mi++)                  \
                _Pragma("unroll") for (int ni = 0; ni < 4; ni++)              \
                    mma8(acc[mi][ni], af[mi], bf[ni]);                        \
        }                                                                     \
    } while (0)

    LOAD_TILE(0);
    cp_commit();
    for (int kt = 0; kt < KT; kt++) {
        if (kt + 1 < KT) LOAD_TILE((kt + 1) & 1);
        cp_commit();
        cp_wait1();
        __syncthreads();
        COMPUTE(kt & 1);
        __syncthreads();
    }
#undef LOAD_TILE
#undef COMPUTE

    // epilogue
#pragma unroll
    for (int mi = 0; mi < 4; mi++) {
        int r0 = rbase + wm + mi * 16 + (lane >> 2);
#pragma unroll
        for (int ni = 0; ni < 4; ni++) {
            int c0 = nbase + wn + ni * 8 + (lane & 3) * 2;
            float b0 = __ldg(&Bias[c0]), b1v = __ldg(&Bias[c0 + 1]);
            float v00 = acc[mi][ni][0] + b0, v01 = acc[mi][ni][1] + b1v;
            float v10 = acc[mi][ni][2] + b0, v11 = acc[mi][ni][3] + b1v;
            if (FC1) {
                v00 = silu(v00); v01 = silu(v01);
                v10 = silu(v10); v11 = silu(v11);
            }
            Out[(size_t)r0 * NTOT + c0]           = v00;
            Out[(size_t)r0 * NTOT + c0 + 1]       = v01;
            Out[(size_t)(r0 + 8) * NTOT + c0]     = v10;
            Out[(size_t)(r0 + 8) * NTOT + c0 + 1] = v11;
        }
    }
}

// ---------------- launch ----------------
extern "C" void kernel_launch(void* const* d_in, const int* in_sizes, int n_in,
                              void* d_out, int out_size) {
    const float* x  = (const float*)d_in[0];
    const float* Wr = (const float*)d_in[1];
    const float* W1 = (const float*)d_in[2];
    const float* b1 = (const float*)d_in[3];
    const float* W2 = (const float*)d_in[4];
    const float* b2 = (const float*)d_in[5];
    float* out = (float*)d_out;

    cudaFuncSetAttribute(k_gemm<true>,  cudaFuncAttributeMaxDynamicSharedMemorySize, 65536);
    cudaFuncSetAttribute(k_gemm<false>, cudaFuncAttributeMaxDynamicSharedMemorySize, 65536);

    k_init<<<(ROWS_PAD + 255) / 256, 256>>>();
    k_router<<<T_TOK / 8, 256>>>(x, Wr);
    k_offsets<<<1, 32>>>();
    k_scatter<<<T_TOK / 256, 256>>>();
    k_gemm<true><<<dim3(FFND / 128, ROWS_PAD / 128), 256, 65536>>>(x, W1, b1);
    k_gemm<false><<<dim3(HID / 128, ROWS_PAD / 128), 256, 65536>>>(nullptr, W2, b2);
    k_combine<<<T_TOK, 256>>>(out);
}